// round 17
// baseline (speedup 1.0000x reference)
#include <cuda_runtime.h>
#include <cuda_fp16.h>
#include <cstdint>

// OnlineHadamard round 17: r16 byte-identical (r10 + streaming cache hints),
// plus: warps with wj==5 skip the jt2==1 MMA cluster (A rows 176-191 are all
// zero padding and all its outputs are discarded by the epilogue guards).

#define KDIM 172
#define MDIM 64
#define NROW 11008
#define NT 384

#define ASTR 368
#define BSTR 144
#define A_BYTES (192 * ASTR)
#define B_BYTES (176 * BSTR)
#define OFF_B0  (A_BYTES)
#define OFF_B1  (A_BYTES + B_BYTES)
#define SMEM_DYN (A_BYTES + 2 * B_BYTES)   // 121344
#define NQUAD 43

__device__ __forceinline__ uint32_t smem_u32(const void* p) {
    uint32_t a;
    asm("{ .reg .u64 t; cvta.to.shared.u64 t, %1; cvt.u32.u64 %0, t; }" : "=r"(a) : "l"(p));
    return a;
}
__device__ __forceinline__ uint32_t h2_u32(__half2 h) {
    uint32_t u;
    *(__half2*)&u = h;
    return u;
}
__device__ __forceinline__ void ldsm_x4(uint32_t* r, uint32_t addr) {
    asm volatile("ldmatrix.sync.aligned.m8n8.x4.shared.b16 {%0,%1,%2,%3}, [%4];"
                 : "=r"(r[0]), "=r"(r[1]), "=r"(r[2]), "=r"(r[3]) : "r"(addr));
}
__device__ __forceinline__ void ldsm_x4t(uint32_t* r, uint32_t addr) {
    asm volatile("ldmatrix.sync.aligned.m8n8.x4.trans.shared.b16 {%0,%1,%2,%3}, [%4];"
                 : "=r"(r[0]), "=r"(r[1]), "=r"(r[2]), "=r"(r[3]) : "r"(addr));
}
__device__ __forceinline__ void mma_f16(float* c, const uint32_t* a, uint32_t b0, uint32_t b1) {
    asm volatile("mma.sync.aligned.m16n8k16.row.col.f32.f16.f16.f32 "
                 "{%0,%1,%2,%3}, {%4,%5,%6,%7}, {%8,%9}, {%0,%1,%2,%3};"
                 : "+f"(c[0]), "+f"(c[1]), "+f"(c[2]), "+f"(c[3])
                 : "r"(a[0]), "r"(a[1]), "r"(a[2]), "r"(a[3]), "r"(b0), "r"(b1));
}

// r10 butterfly verbatim: 8 elems/thread, m = {4tg..4tg+3, 32+4tg..32+4tg+3}.
__device__ __forceinline__ void bfly8_store(float4 lo, float4 hi, char* bbuf,
                                            int c, int tg, float scale) {
    float v[8] = {lo.x, lo.y, lo.z, lo.w, hi.x, hi.y, hi.z, hi.w};
    float t;
    #pragma unroll
    for (int i = 0; i < 4; i++) { t = v[i]; v[i] = t + v[i+4]; v[i+4] = t - v[i+4]; }
    #pragma unroll
    for (int g2 = 0; g2 < 8; g2 += 2) { t = v[g2]; v[g2] = t + v[g2+1]; v[g2+1] = t - v[g2+1]; }
    #pragma unroll
    for (int b = 0; b < 8; b += 4)
        #pragma unroll
        for (int i = 0; i < 2; i++) {
            t = v[b+i]; v[b+i] = t + v[b+i+2]; v[b+i+2] = t - v[b+i+2];
        }
    #pragma unroll
    for (int s = 1; s <= 4; s <<= 1) {
        bool up = (tg & s) != 0;
        #pragma unroll
        for (int i = 0; i < 8; i++) {
            float q = __shfl_xor_sync(0xffffffffu, v[i], s);
            v[i] = up ? (q - v[i]) : (v[i] + q);
        }
    }
    uint32_t h01 = h2_u32(__floats2half2_rn(v[0]*scale, v[1]*scale));
    uint32_t h23 = h2_u32(__floats2half2_rn(v[2]*scale, v[3]*scale));
    uint32_t h45 = h2_u32(__floats2half2_rn(v[4]*scale, v[5]*scale));
    uint32_t h67 = h2_u32(__floats2half2_rn(v[6]*scale, v[7]*scale));
    *(uint2*)(bbuf + c * BSTR + tg * 8)      = make_uint2(h01, h23);
    *(uint2*)(bbuf + c * BSTR + 64 + tg * 8) = make_uint2(h45, h67);
}

__global__ __launch_bounds__(NT, 1)
void onl_had_r17_kernel(const float* __restrict__ x,
                        const float* __restrict__ had,
                        float* __restrict__ out, int rows)
{
    extern __shared__ char sm[];
    const uint32_t sbase = smem_u32(sm);
    const int tid = threadIdx.x, lane = tid & 31, warp = tid >> 5;
    const int tg = lane & 7, g = lane >> 3;

    // ---- one-time: A = had (fp16), zero-padded to 192x176 ----
    for (int idx = tid; idx < 192 * 176; idx += NT) {
        int j = idx / 176, k = idx - j * 176;
        float v = (j < KDIM && k < KDIM) ? had[j * KDIM + k] : 0.0f;
        *(__half*)(sm + j * ASTR + 2 * k) = __float2half_rn(v);
    }
    for (int idx = tid; idx < 2 * 4 * 64; idx += NT) {
        int b = idx >> 8, r = (idx >> 6) & 3, m = idx & 63;
        char* p = sm + (b ? OFF_B1 : OFF_B0) + (172 + r) * BSTR;
        *(__half*)(p + 2 * m) = __float2half_rn(0.0f);
    }
    __syncthreads();

    const float scale = rsqrtf((float)NROW);
    const int stride = gridDim.x;

    // ---- warp tile: wj 0..5 (32 j), wm 0..1 (32 m) ----
    const int wj = warp >> 1, wm = warp & 1;
    const bool full_tile = (wj != 5);   // wj==5, jt2==1 covers only zero padding
    uint32_t a_frag[2][11][4];
    #pragma unroll
    for (int jt2 = 0; jt2 < 2; jt2++) {
        uint32_t a_addr = sbase
            + (uint32_t)((wj * 32 + jt2 * 16) + (lane & 7) + ((lane >> 3) & 1) * 8) * ASTR
            + (uint32_t)((lane >> 4) * 16);
        #pragma unroll
        for (int kt = 0; kt < 11; kt++)
            ldsm_x4(a_frag[jt2][kt], a_addr + kt * 32);
    }

    uint32_t b_lane_off = (uint32_t)((lane & 15) * BSTR + (lane >> 4) * 16 + wm * 64);
    const int eq = lane & 3, er = lane >> 2;
    const uint32_t xoff = (uint32_t)(g * 64 + tg * 4);

    int row0 = blockIdx.x;
    if (row0 < rows) {
        const float* xr = x + (size_t)row0 * NROW;
        #pragma unroll
        for (int p = 0; p < 4; p++) {
            int q = warp + 12 * p;
            if (q < NQUAD) {
                const float* b = xr + q * 256 + xoff;
                bfly8_store(__ldcs((const float4*)b), __ldcs((const float4*)(b + 32)),
                            sm + OFF_B0, 4 * q + g, tg, scale);
            }
        }
    }
    __syncthreads();

    int buf = 0;
    for (int row = row0; row < rows; row += stride) {
        const int nxt = row + stride;
        const bool have_nxt = nxt < rows;
        char* bnext = sm + (buf ? OFF_B0 : OFF_B1);

        // -- prefetch next row's quads (streaming loads, retire under GEMM) --
        float4 pfl[4], pfh[4];
        if (have_nxt) {
            const float* xn = x + (size_t)nxt * NROW;
            #pragma unroll
            for (int p = 0; p < 4; p++) {
                int q = warp + 12 * p;
                if (q < NQUAD) {
                    const float* b = xn + q * 256 + xoff;
                    pfl[p] = __ldcs((const float4*)b);
                    pfh[p] = __ldcs((const float4*)(b + 32));
                }
            }
        }

        // -------- GEMM row i: 32j x 32m per warp --------
        uint32_t bbase = sbase + (buf ? OFF_B1 : OFF_B0) + b_lane_off;
        float acc[2][4][4];
        #pragma unroll
        for (int jt2 = 0; jt2 < 2; jt2++)
            #pragma unroll
            for (int n = 0; n < 4; n++)
                acc[jt2][n][0] = acc[jt2][n][1] = acc[jt2][n][2] = acc[jt2][n][3] = 0.f;

        #pragma unroll
        for (int kt = 0; kt < 11; kt++) {
            uint32_t bk = bbase + (uint32_t)(kt * 16 * BSTR);
            uint32_t b0[4], b1[4];
            ldsm_x4t(b0, bk);
            ldsm_x4t(b1, bk + 32);
            mma_f16(acc[0][0], a_frag[0][kt], b0[0], b0[1]);
            mma_f16(acc[0][1], a_frag[0][kt], b0[2], b0[3]);
            mma_f16(acc[0][2], a_frag[0][kt], b1[0], b1[1]);
            mma_f16(acc[0][3], a_frag[0][kt], b1[2], b1[3]);
            if (full_tile) {   // warp-uniform; skips all-zero discarded tile
                mma_f16(acc[1][0], a_frag[1][kt], b0[0], b0[1]);
                mma_f16(acc[1][1], a_frag[1][kt], b0[2], b0[3]);
                mma_f16(acc[1][2], a_frag[1][kt], b1[0], b1[1]);
                mma_f16(acc[1][3], a_frag[1][kt], b1[2], b1[3]);
            }
        }

        // -------- epilogue: streaming stores (r10 addressing) --------
        {
            float* orow = out + (size_t)row * NROW + wm * 32 + eq * 2;
            #pragma unroll
            for (int jt2 = 0; jt2 < 2; jt2++) {
                int j1 = wj * 32 + jt2 * 16 + er;
                int j2 = j1 + 8;
                if (j1 < KDIM) {
                    float* o1 = orow + j1 * MDIM;
                    #pragma unroll
                    for (int n = 0; n < 4; n++)
                        __stcs((float2*)(o1 + n * 8), make_float2(acc[jt2][n][0], acc[jt2][n][1]));
                }
                if (j2 < KDIM) {
                    float* o2 = orow + j2 * MDIM;
                    #pragma unroll
                    for (int n = 0; n < 4; n++)
                        __stcs((float2*)(o2 + n * 8), make_float2(acc[jt2][n][2], acc[jt2][n][3]));
                }
            }
        }

        // -- butterfly next row from prefetched regs --
        if (have_nxt) {
            #pragma unroll
            for (int p = 0; p < 4; p++) {
                int q = warp + 12 * p;
                if (q < NQUAD)
                    bfly8_store(pfl[p], pfh[p], bnext, 4 * q + g, tg, scale);
            }
        }
        buf ^= 1;
        __syncthreads();
    }
}

extern "C" void kernel_launch(void* const* d_in, const int* in_sizes, int n_in,
                              void* d_out, int out_size) {
    const float* x   = (const float*)d_in[0];
    const float* had = (const float*)d_in[1];
    float* out = (float*)d_out;
    int rows = in_sizes[0] / NROW;

    cudaFuncSetAttribute(onl_had_r17_kernel,
                         cudaFuncAttributeMaxDynamicSharedMemorySize, SMEM_DYN);
    int grid = rows < 152 ? rows : 152;
    onl_had_r17_kernel<<<grid, NT, SMEM_DYN>>>(x, had, out, rows);
}